// round 3
// baseline (speedup 1.0000x reference)
#include <cuda_runtime.h>
#include <cuda_bf16.h>

// Problem constants
#define Bc 2
#define Lc 4096
#define Hc 8
#define Dc 64
#define Mc 128
#define BH 16          // B*H
#define NCH 64         // chunks per (b,h), chunk length 64
#define NROWS (Bc*Lc*Hc)   // 65536

typedef unsigned long long ull;

// ---- f32x2 helpers (sm_103a packed fp32 FMA, PTX-only path) ----
__device__ __forceinline__ ull pack2(float a, float b) {
    ull r;
    asm("mov.b64 %0, {%1, %2};" : "=l"(r) : "r"(__float_as_uint(a)), "r"(__float_as_uint(b)));
    return r;
}
__device__ __forceinline__ ull bcast2(float a) { return pack2(a, a); }
__device__ __forceinline__ void unpack2(ull v, float& a, float& b) {
    unsigned int x, y;
    asm("mov.b64 {%0, %1}, %2;" : "=r"(x), "=r"(y) : "l"(v));
    a = __uint_as_float(x); b = __uint_as_float(y);
}
__device__ __forceinline__ void ffma2(ull& acc, ull a, ull b) {
    asm("fma.rn.f32x2 %0, %1, %2, %0;" : "+l"(acc) : "l"(a), "l"(b));
}

// Scratch (device globals; no allocation allowed)
__device__ float g_qp[BH * Lc * Mc];            // [bh][l][m]
__device__ float g_kp[BH * Lc * Mc];            // [bh][l][m]
__device__ float g_state[BH * NCH * Dc * Mc];   // per chunk: [m][d] (m-major), becomes exclusive prefix
__device__ float g_ksum[BH * NCH * Mc];         // per chunk: [m], becomes exclusive prefix

// ---------------------------------------------------------------------------
// Kernel 1: projection + relu + eps.  grid (2048, 2): y=0 -> query, y=1 -> key
// ---------------------------------------------------------------------------
__global__ void proj_kernel(const float* __restrict__ qg,
                            const float* __restrict__ kg,
                            const float* __restrict__ pg)
{
    __shared__ float p_s[128 * 65];   // proj [m][d], pitch 65 (odd -> conflict free)
    __shared__ float row_s[32 * 64];  // input rows

    const float* inp  = blockIdx.y ? kg : qg;
    float*       outp = blockIdx.y ? g_kp : g_qp;

    int tid = threadIdx.x;

    const float4* p4 = (const float4*)pg;
    #pragma unroll
    for (int t = tid; t < 2048; t += 256) {
        float4 v = p4[t];
        int m = t >> 4;
        int d = (t & 15) * 4;
        float* dst = &p_s[m * 65 + d];
        dst[0] = v.x; dst[1] = v.y; dst[2] = v.z; dst[3] = v.w;
    }

    int rowbase = blockIdx.x * 32;
    const float4* in4 = (const float4*)(inp + (size_t)rowbase * 64);
    float4* rs4 = (float4*)row_s;
    rs4[tid]       = in4[tid];
    rs4[tid + 256] = in4[tid + 256];
    __syncthreads();

    int mg = tid & 31;
    int rg = tid >> 5;
    int r0 = rg * 4;

    float acc[4][4];
    #pragma unroll
    for (int r = 0; r < 4; r++)
        #pragma unroll
        for (int i = 0; i < 4; i++) acc[r][i] = 0.f;

    #pragma unroll 8
    for (int d = 0; d < 64; d++) {
        float pv[4], rv[4];
        #pragma unroll
        for (int i = 0; i < 4; i++) pv[i] = p_s[(mg + 32 * i) * 65 + d];
        #pragma unroll
        for (int r = 0; r < 4; r++) rv[r] = row_s[(r0 + r) * 64 + d];
        #pragma unroll
        for (int r = 0; r < 4; r++)
            #pragma unroll
            for (int i = 0; i < 4; i++)
                acc[r][i] = fmaf(rv[r], pv[i], acc[r][i]);
    }

    const float ratio = 0.08838834764831845f;  // 1/sqrt(128)
    #pragma unroll
    for (int r = 0; r < 4; r++) {
        int rid = rowbase + r0 + r;
        int b = rid >> 15;
        int l = (rid >> 3) & 4095;
        int h = rid & 7;
        size_t off = ((size_t)(b * 8 + h) * Lc + l) * Mc;
        #pragma unroll
        for (int i = 0; i < 4; i++) {
            float val = acc[r][i] * ratio;
            val = (val > 0.f ? val : 0.f) + 1e-3f;
            outp[off + mg + 32 * i] = val;
        }
    }
}

// ---------------------------------------------------------------------------
// Kernel 2: per-chunk S = K_c^T V_c (stored m-major [m][d]) and z = sum_k.
// grid 1024 = bh*64 + c, 256 threads.  FFMA2 inner loop.
// ---------------------------------------------------------------------------
__global__ void chunk_kernel(const float* __restrict__ vg)
{
    __shared__ float k_s[64 * 128];  // [c][m]
    __shared__ float v_s[64 * 64];   // [c][d]

    int tid = threadIdx.x;
    int bh  = blockIdx.x >> 6;
    int c   = blockIdx.x & 63;
    int b = bh >> 3, h = bh & 7;

    const float4* kp4 = (const float4*)&g_kp[((size_t)bh * Lc + c * 64) * Mc];
    float4* ks4 = (float4*)k_s;
    #pragma unroll
    for (int t = 0; t < 8; t++) ks4[tid + t * 256] = kp4[tid + t * 256];

    #pragma unroll
    for (int t = tid; t < 1024; t += 256) {
        int row = t >> 4, col = t & 15;
        int l = c * 64 + row;
        const float4* src = (const float4*)(vg + (((size_t)b * Lc + l) * Hc + h) * Dc);
        ((float4*)(v_s + row * 64))[col] = src[col];
    }
    __syncthreads();

    int mg = tid & 31, dg = tid >> 5;
    int m0 = mg * 4, d0 = dg * 8;
    ull acc2[4][4];
    #pragma unroll
    for (int i = 0; i < 4; i++)
        #pragma unroll
        for (int j = 0; j < 4; j++) acc2[i][j] = 0ull;

    #pragma unroll 4
    for (int cc = 0; cc < 64; cc++) {
        float4 kv = *(const float4*)&k_s[cc * 128 + m0];
        ulonglong2 va = *(const ulonglong2*)&v_s[cc * 64 + d0];
        ulonglong2 vb = *(const ulonglong2*)&v_s[cc * 64 + d0 + 4];
        ull kb[4] = {bcast2(kv.x), bcast2(kv.y), bcast2(kv.z), bcast2(kv.w)};
        #pragma unroll
        for (int i = 0; i < 4; i++) {
            ffma2(acc2[i][0], kb[i], va.x);
            ffma2(acc2[i][1], kb[i], va.y);
            ffma2(acc2[i][2], kb[i], vb.x);
            ffma2(acc2[i][3], kb[i], vb.y);
        }
    }

    // store S m-major: [m][d], float4 over d
    float* Sp = &g_state[(size_t)blockIdx.x * (Dc * Mc)];
    #pragma unroll
    for (int i = 0; i < 4; i++) {
        float f0,f1,f2,f3,f4,f5,f6,f7;
        unpack2(acc2[i][0], f0, f1);
        unpack2(acc2[i][1], f2, f3);
        unpack2(acc2[i][2], f4, f5);
        unpack2(acc2[i][3], f6, f7);
        *(float4*)&Sp[(m0 + i) * 64 + d0]     = make_float4(f0, f1, f2, f3);
        *(float4*)&Sp[(m0 + i) * 64 + d0 + 4] = make_float4(f4, f5, f6, f7);
    }

    // z[m]
    if (tid < 128) {
        float z = 0.f;
        #pragma unroll 8
        for (int cc = 0; cc < 64; cc++) z += k_s[cc * 128 + tid];
        g_ksum[(size_t)blockIdx.x * Mc + tid] = z;
    }
}

// ---------------------------------------------------------------------------
// Kernel 3: exclusive prefix over chunks (in place, layout-agnostic).
// ---------------------------------------------------------------------------
__global__ void prefix_kernel()
{
    int bh    = blockIdx.x >> 5;
    int slice = blockIdx.x & 31;
    int e = slice * 256 + threadIdx.x;            // 0..8191
    size_t base = (size_t)bh * NCH * (Dc * Mc) + e;

    float acc = 0.f;
    #pragma unroll 1
    for (int c0 = 0; c0 < 64; c0 += 8) {
        float v[8];
        #pragma unroll
        for (int u = 0; u < 8; u++) v[u] = g_state[base + (size_t)(c0 + u) * (Dc * Mc)];
        #pragma unroll
        for (int u = 0; u < 8; u++) {
            g_state[base + (size_t)(c0 + u) * (Dc * Mc)] = acc;
            acc += v[u];
        }
    }

    if (slice == 0 && threadIdx.x < 128) {
        size_t kb = (size_t)bh * NCH * Mc + threadIdx.x;
        float a2 = 0.f;
        #pragma unroll 1
        for (int c = 0; c < 64; c++) {
            float t = g_ksum[kb + (size_t)c * Mc];
            g_ksum[kb + (size_t)c * Mc] = a2;
            a2 += t;
        }
    }
}

// ---------------------------------------------------------------------------
// Kernel 4: intra-chunk attention + state contribution + normalize.
// Q and K stored contraction-major [m][col] with float4-group XOR swizzle.
// K buffer unioned with state buffer (phase1 vs phase2). 2 CTAs/SM.
// ---------------------------------------------------------------------------
#define CMP 68   // contraction-major pitch (m rows, 64 cols + pad, 17 groups)
#define VP  68
#define AP  65
#define SM4_FLOATS (128*CMP /*q*/ + 128*CMP /*k|st union*/ + 64*VP + 64*AP + 128 + 64)

// swizzled float-index of element (m, col) in a contraction-major array
__device__ __forceinline__ int cm_idx(int m, int col) {
    return m * CMP + 4 * ((col >> 2) ^ (m & 15)) + (col & 3);
}

__global__ void __launch_bounds__(256, 2)
out_kernel(const float* __restrict__ vg, float* __restrict__ outg)
{
    extern __shared__ float sm[];
    float* q_s  = sm;                    // [m][i] swizzled, pitch 68
    float* u_s  = q_s + 128 * CMP;       // union: k [m][j] swizzled / st [m][d] plain
    float* v_s  = u_s + 128 * CMP;       // [j][d] pitch 68
    float* a_s  = v_s + 64 * VP;         // [i][j] pitch 65
    float* ks_s = a_s + 64 * AP;         // [m]
    float* den_s = ks_s + 128;           // [i]

    int tid = threadIdx.x;
    int bh  = blockIdx.x >> 6;
    int c   = blockIdx.x & 63;
    int b = bh >> 3, h = bh & 7;

    const float4* qsrc = (const float4*)&g_qp[((size_t)bh * Lc + c * 64) * Mc];
    const float4* ksrc = (const float4*)&g_kp[((size_t)bh * Lc + c * 64) * Mc];
    const float4* ssrc = (const float4*)&g_state[(size_t)blockIdx.x * (Dc * Mc)];

    // Prefetch state tile into registers (m-major: t -> (m=t>>4, d0=(t&15)*4))
    float4 stv[8];
    #pragma unroll
    for (int k2 = 0; k2 < 8; k2++) stv[k2] = ssrc[tid + k2 * 256];

    // Q transpose: global [row][m] -> smem [m][row] swizzled
    #pragma unroll
    for (int t = tid; t < 2048; t += 256) {
        float4 w = qsrc[t];
        int row = t >> 5;
        int m0 = (t & 31) * 4;
        q_s[cm_idx(m0 + 0, row)] = w.x;
        q_s[cm_idx(m0 + 1, row)] = w.y;
        q_s[cm_idx(m0 + 2, row)] = w.z;
        q_s[cm_idx(m0 + 3, row)] = w.w;
    }
    // K transpose into union buffer
    #pragma unroll
    for (int t = tid; t < 2048; t += 256) {
        float4 w = ksrc[t];
        int row = t >> 5;
        int m0 = (t & 31) * 4;
        u_s[cm_idx(m0 + 0, row)] = w.x;
        u_s[cm_idx(m0 + 1, row)] = w.y;
        u_s[cm_idx(m0 + 2, row)] = w.z;
        u_s[cm_idx(m0 + 3, row)] = w.w;
    }
    // V
    #pragma unroll
    for (int t = tid; t < 1024; t += 256) {
        int row = t >> 4, col = t & 15;
        int l = c * 64 + row;
        const float4* src = (const float4*)(vg + (((size_t)b * Lc + l) * Hc + h) * Dc);
        *(float4*)&v_s[row * VP + col * 4] = src[col];
    }
    if (tid < 128) ks_s[tid] = g_ksum[(size_t)blockIdx.x * Mc + tid];
    __syncthreads();

    // --- phase 1: A = Q K^T (masked), FFMA2 ---
    {
        int jg = tid & 15, ig = tid >> 4;
        int i0 = ig * 4, j0 = jg * 4;
        ull acc[4][2];
        #pragma unroll
        for (int x = 0; x < 4; x++) { acc[x][0] = 0ull; acc[x][1] = 0ull; }

        if (j0 <= i0 + 3) {
            #pragma unroll 2
            for (int m = 0; m < 128; m++) {
                ulonglong2 qv = *(const ulonglong2*)&q_s[m * CMP + 4 * (ig ^ (m & 15))];
                ulonglong2 kv = *(const ulonglong2*)&u_s[m * CMP + 4 * (jg ^ (m & 15))];
                float q0, q1, q2, q3;
                unpack2(qv.x, q0, q1);
                unpack2(qv.y, q2, q3);
                ull qb0 = bcast2(q0), qb1 = bcast2(q1), qb2 = bcast2(q2), qb3 = bcast2(q3);
                ffma2(acc[0][0], qb0, kv.x); ffma2(acc[0][1], qb0, kv.y);
                ffma2(acc[1][0], qb1, kv.x); ffma2(acc[1][1], qb1, kv.y);
                ffma2(acc[2][0], qb2, kv.x); ffma2(acc[2][1], qb2, kv.y);
                ffma2(acc[3][0], qb3, kv.x); ffma2(acc[3][1], qb3, kv.y);
            }
        }
        #pragma unroll
        for (int x = 0; x < 4; x++) {
            int i = i0 + x;
            float a0, a1, a2, a3;
            unpack2(acc[x][0], a0, a1);
            unpack2(acc[x][1], a2, a3);
            a_s[i * AP + j0 + 0] = (j0 + 0 <= i) ? a0 : 0.f;
            a_s[i * AP + j0 + 1] = (j0 + 1 <= i) ? a1 : 0.f;
            a_s[i * AP + j0 + 2] = (j0 + 2 <= i) ? a2 : 0.f;
            a_s[i * AP + j0 + 3] = (j0 + 3 <= i) ? a3 : 0.f;
        }
    }
    __syncthreads();   // all k reads done; a_s complete

    // scatter prefetched state into union buffer: [m][d] plain pitch 68
    #pragma unroll
    for (int k2 = 0; k2 < 8; k2++) {
        int t = tid + k2 * 256;
        *(float4*)&u_s[(t >> 4) * CMP + (t & 15) * 4] = stv[k2];
    }

    // den (uses q_s, ks_s, a_s — not the union buffer)
    if (tid < 64) {
        int i = tid;
        float dd = 0.f;
        #pragma unroll 4
        for (int m = 0; m < 128; m++) dd = fmaf(q_s[cm_idx(m, i)], ks_s[m], dd);
        for (int j = 0; j <= i; j++) dd += a_s[i * AP + j];
        den_s[i] = dd;
    }
    __syncthreads();

    // --- phase 2: num = Q*state + A*V, normalize.  FFMA2 ---
    int dg = tid & 7, igp = tid >> 3;
    int d0 = dg * 8, i0 = igp * 2;

    ull num0[4], num1[4];
    #pragma unroll
    for (int p = 0; p < 4; p++) { num0[p] = 0ull; num1[p] = 0ull; }

    {
        int grp = igp >> 1, off = i0 & 3;   // q pair (i0,i0+1) lies inside one 4-group
        #pragma unroll 2
        for (int m = 0; m < 128; m++) {
            ull qp = *(const ull*)&q_s[m * CMP + 4 * (grp ^ (m & 15)) + off];
            float q0, q1; unpack2(qp, q0, q1);
            ull qb0 = bcast2(q0), qb1 = bcast2(q1);
            ulonglong2 s0 = *(const ulonglong2*)&u_s[m * CMP + d0];
            ulonglong2 s1 = *(const ulonglong2*)&u_s[m * CMP + d0 + 4];
            ffma2(num0[0], qb0, s0.x); ffma2(num0[1], qb0, s0.y);
            ffma2(num0[2], qb0, s1.x); ffma2(num0[3], qb0, s1.y);
            ffma2(num1[0], qb1, s0.x); ffma2(num1[1], qb1, s0.y);
            ffma2(num1[2], qb1, s1.x); ffma2(num1[3], qb1, s1.y);
        }
    }

    #pragma unroll 2
    for (int j = 0; j <= i0 + 1; j++) {
        float a0 = a_s[i0 * AP + j];
        float a1 = a_s[(i0 + 1) * AP + j];
        ull ab0 = bcast2(a0), ab1 = bcast2(a1);
        ulonglong2 w0 = *(const ulonglong2*)&v_s[j * VP + d0];
        ulonglong2 w1 = *(const ulonglong2*)&v_s[j * VP + d0 + 4];
        ffma2(num0[0], ab0, w0.x); ffma2(num0[1], ab0, w0.y);
        ffma2(num0[2], ab0, w1.x); ffma2(num0[3], ab0, w1.y);
        ffma2(num1[0], ab1, w0.x); ffma2(num1[1], ab1, w0.y);
        ffma2(num1[2], ab1, w1.x); ffma2(num1[3], ab1, w1.y);
    }

    // write out
    {
        float f[2][8];
        unpack2(num0[0], f[0][0], f[0][1]); unpack2(num0[1], f[0][2], f[0][3]);
        unpack2(num0[2], f[0][4], f[0][5]); unpack2(num0[3], f[0][6], f[0][7]);
        unpack2(num1[0], f[1][0], f[1][1]); unpack2(num1[1], f[1][2], f[1][3]);
        unpack2(num1[2], f[1][4], f[1][5]); unpack2(num1[3], f[1][6], f[1][7]);
        #pragma unroll
        for (int r = 0; r < 2; r++) {
            int i = i0 + r;
            int l = c * 64 + i;
            float inv = __fdividef(1.f, den_s[i]);
            float* orow = outg + (((size_t)b * Lc + l) * Hc + h) * Dc;
            *(float4*)&orow[d0]     = make_float4(f[r][0]*inv, f[r][1]*inv, f[r][2]*inv, f[r][3]*inv);
            *(float4*)&orow[d0 + 4] = make_float4(f[r][4]*inv, f[r][5]*inv, f[r][6]*inv, f[r][7]*inv);
        }
    }
}

// ---------------------------------------------------------------------------
extern "C" void kernel_launch(void* const* d_in, const int* in_sizes, int n_in,
                              void* d_out, int out_size)
{
    const float* q    = (const float*)d_in[0];
    const float* k    = (const float*)d_in[1];
    const float* v    = (const float*)d_in[2];
    const float* proj = (const float*)d_in[3];
    float* out = (float*)d_out;

    cudaFuncSetAttribute(out_kernel, cudaFuncAttributeMaxDynamicSharedMemorySize,
                         SM4_FLOATS * (int)sizeof(float));

    proj_kernel<<<dim3(NROWS / 32, 2), 256>>>(q, k, proj);
    chunk_kernel<<<BH * NCH, 256>>>(v);
    prefix_kernel<<<BH * 32, 256>>>();
    out_kernel<<<BH * NCH, 256, SM4_FLOATS * (int)sizeof(float)>>>(v, out);
}

// round 5
// speedup vs baseline: 1.1530x; 1.1530x over previous
#include <cuda_runtime.h>
#include <cuda_bf16.h>

// Problem constants
#define Bc 2
#define Lc 4096
#define Hc 8
#define Dc 64
#define Mc 128
#define BH 16          // B*H
#define NCH 64         // chunks per (b,h), chunk length 64
#define NROWS (Bc*Lc*Hc)   // 65536

typedef unsigned long long ull;

// ---- f32x2 helpers (sm_103a packed fp32 FMA, PTX-only path) ----
__device__ __forceinline__ ull pack2(float a, float b) {
    ull r;
    asm("mov.b64 %0, {%1, %2};" : "=l"(r) : "r"(__float_as_uint(a)), "r"(__float_as_uint(b)));
    return r;
}
__device__ __forceinline__ ull bcast2(float a) { return pack2(a, a); }
__device__ __forceinline__ void unpack2(ull v, float& a, float& b) {
    unsigned int x, y;
    asm("mov.b64 {%0, %1}, %2;" : "=r"(x), "=r"(y) : "l"(v));
    a = __uint_as_float(x); b = __uint_as_float(y);
}
__device__ __forceinline__ void ffma2(ull& acc, ull a, ull b) {
    asm("fma.rn.f32x2 %0, %1, %2, %0;" : "+l"(acc) : "l"(a), "l"(b));
}

// Scratch. g_qp/g_kp layout: [bh][chunk][m(128)][r(64)]  (contraction-major per chunk)
// g_state per chunk: [m(128)][d(64)]  (m-major)
__device__ float g_qp[BH * Lc * Mc];
__device__ float g_kp[BH * Lc * Mc];
__device__ float g_state[BH * NCH * Dc * Mc];
__device__ float g_ksum[BH * NCH * Mc];

// ---------------------------------------------------------------------------
// Kernel 1: projection + relu + eps.
// grid 2048: bid = qk*1024 + bh*64 + chunk.  Block covers 64 rows (one chunk)
// of one (b,h); output tile [m][64] written direct from registers.
// ---------------------------------------------------------------------------
#define PJ_PT 132   // p_T pitch  ([d][m], m fast)
#define PJ_RT 68    // rows_T pitch ([d][r], r fast)
#define PJ_SMEM (64*PJ_PT + 64*PJ_RT)

__global__ void __launch_bounds__(256, 2)
proj_kernel(const float* __restrict__ qg,
            const float* __restrict__ kg,
            const float* __restrict__ pg)
{
    extern __shared__ float psm[];
    float* p_T    = psm;                // [d][m] pitch 132
    float* rows_T = psm + 64 * PJ_PT;   // [d][r] pitch 68

    int bid = blockIdx.x;
    int qk  = bid >> 10;
    int bh  = (bid >> 6) & 15;
    int ck  = bid & 63;
    int b = bh >> 3, h = bh & 7;

    const float* inp  = qk ? kg : qg;
    float*       outp = (qk ? g_kp : g_qp) + ((size_t)bh * Lc + ck * 64) * Mc;  // tile [m][64]

    int tid = threadIdx.x;

    // load projection matrix [m][64] -> p_T [d][m]  (scalar scatter, modest conflicts, one-time)
    const float4* p4 = (const float4*)pg;
    #pragma unroll
    for (int t = tid; t < 2048; t += 256) {
        float4 v = p4[t];
        int m = t >> 4;
        int d0 = (t & 15) * 4;
        p_T[(d0 + 0) * PJ_PT + m] = v.x;
        p_T[(d0 + 1) * PJ_PT + m] = v.y;
        p_T[(d0 + 2) * PJ_PT + m] = v.z;
        p_T[(d0 + 3) * PJ_PT + m] = v.w;
    }

    // load 64 rows (strided in global) -> rows_T [d][r]
    #pragma unroll
    for (int t = tid; t < 1024; t += 256) {
        int r = t >> 4;
        int d0 = (t & 15) * 4;
        int l = ck * 64 + r;
        const float4* src = (const float4*)(inp + (((size_t)b * Lc + l) * Hc + h) * Dc);
        float4 v = src[t & 15];
        rows_T[(d0 + 0) * PJ_RT + r] = v.x;
        rows_T[(d0 + 1) * PJ_RT + r] = v.y;
        rows_T[(d0 + 2) * PJ_RT + r] = v.z;
        rows_T[(d0 + 3) * PJ_RT + r] = v.w;
    }
    __syncthreads();

    // GEMM: thread (mg, rg): m = 4*mg..4*mg+3, rows r0 = 8*rg..+7
    int mg = tid & 31;
    int rg = tid >> 5;
    int m0 = 4 * mg, r0 = 8 * rg;

    ull acc2[4][4];   // [r-pair][m]
    #pragma unroll
    for (int a = 0; a < 4; a++)
        #pragma unroll
        for (int c = 0; c < 4; c++) acc2[a][c] = 0ull;

    #pragma unroll 4
    for (int d = 0; d < 64; d++) {
        float4 pv = *(const float4*)&p_T[d * PJ_PT + m0];
        float4 rv0 = *(const float4*)&rows_T[d * PJ_RT + r0];
        float4 rv1 = *(const float4*)&rows_T[d * PJ_RT + r0 + 4];
        ull rp[4] = { pack2(rv0.x, rv0.y), pack2(rv0.z, rv0.w),
                      pack2(rv1.x, rv1.y), pack2(rv1.z, rv1.w) };
        ull pb[4] = { bcast2(pv.x), bcast2(pv.y), bcast2(pv.z), bcast2(pv.w) };
        #pragma unroll
        for (int a = 0; a < 4; a++)
            #pragma unroll
            for (int c = 0; c < 4; c++)
                ffma2(acc2[a][c], rp[a], pb[c]);
    }

    const float ratio = 0.08838834764831845f;  // 1/sqrt(128)
    #pragma unroll
    for (int c = 0; c < 4; c++) {
        int m = m0 + c;
        float f[8];
        #pragma unroll
        for (int a = 0; a < 4; a++) unpack2(acc2[a][c], f[2*a], f[2*a+1]);
        #pragma unroll
        for (int u = 0; u < 8; u++) {
            float val = f[u] * ratio;
            f[u] = (val > 0.f ? val : 0.f) + 1e-3f;
        }
        *(float4*)&outp[m * 64 + r0]     = make_float4(f[0], f[1], f[2], f[3]);
        *(float4*)&outp[m * 64 + r0 + 4] = make_float4(f[4], f[5], f[6], f[7]);
    }
}

// ---------------------------------------------------------------------------
// Kernel 2: per-chunk S[m][d] = sum_c k[c][m] v[c][d], z[m] = sum_c k[c][m].
// K^T global layout [m][64 c]. grid 1024 = bh*64 + c.
// ---------------------------------------------------------------------------
#define CK_KP 65     // kT_s pitch (odd -> conflict-free scalar)
#define CK_VP 68
#define CK_SMEM (128*CK_KP + 64*CK_VP)

__global__ void __launch_bounds__(256, 2)
chunk_kernel(const float* __restrict__ vg)
{
    extern __shared__ float csm[];
    float* kT_s = csm;                 // [m][c] pitch 65
    float* v_s  = csm + 128 * CK_KP;   // [c][d] pitch 68

    int tid = threadIdx.x;
    int bh  = blockIdx.x >> 6;
    int c   = blockIdx.x & 63;
    int b = bh >> 3, h = bh & 7;

    // K^T tile: contiguous [m][64] in global -> scalar copy (coalesced, CF stores)
    const float* ksrc = &g_kp[((size_t)bh * Lc + c * 64) * Mc];
    #pragma unroll
    for (int t = tid; t < 8192; t += 256) {
        int m = t >> 6, cc = t & 63;
        kT_s[m * CK_KP + cc] = ksrc[t];
    }

    // V chunk
    #pragma unroll
    for (int t = tid; t < 1024; t += 256) {
        int row = t >> 4, col = t & 15;
        int l = c * 64 + row;
        const float4* src = (const float4*)(vg + (((size_t)b * Lc + l) * Hc + h) * Dc);
        *(float4*)&v_s[row * CK_VP + col * 4] = src[col];
    }
    __syncthreads();

    // thread (mg, dg): m = mg + 32*i, d0 = dg*8
    int mg = tid & 31, dg = tid >> 5;
    int d0 = dg * 8;
    ull acc2[4][4];
    #pragma unroll
    for (int i = 0; i < 4; i++)
        #pragma unroll
        for (int j = 0; j < 4; j++) acc2[i][j] = 0ull;

    #pragma unroll 4
    for (int cc = 0; cc < 64; cc++) {
        ulonglong2 va = *(const ulonglong2*)&v_s[cc * CK_VP + d0];
        ulonglong2 vb = *(const ulonglong2*)&v_s[cc * CK_VP + d0 + 4];
        #pragma unroll
        for (int i = 0; i < 4; i++) {
            ull kb = bcast2(kT_s[(mg + 32 * i) * CK_KP + cc]);
            ffma2(acc2[i][0], kb, va.x);
            ffma2(acc2[i][1], kb, va.y);
            ffma2(acc2[i][2], kb, vb.x);
            ffma2(acc2[i][3], kb, vb.y);
        }
    }

    // store S [m][d] (16B-scattered sectors; L2 merges within the tile)
    float* Sp = &g_state[(size_t)blockIdx.x * (Dc * Mc)];
    #pragma unroll
    for (int i = 0; i < 4; i++) {
        int m = mg + 32 * i;
        float f0,f1,f2,f3,f4,f5,f6,f7;
        unpack2(acc2[i][0], f0, f1);
        unpack2(acc2[i][1], f2, f3);
        unpack2(acc2[i][2], f4, f5);
        unpack2(acc2[i][3], f6, f7);
        *(float4*)&Sp[m * 64 + d0]     = make_float4(f0, f1, f2, f3);
        *(float4*)&Sp[m * 64 + d0 + 4] = make_float4(f4, f5, f6, f7);
    }

    // z[m]
    if (tid < 128) {
        float z = 0.f;
        #pragma unroll 8
        for (int cc = 0; cc < 64; cc++) z += kT_s[tid * CK_KP + cc];
        g_ksum[(size_t)blockIdx.x * Mc + tid] = z;
    }
}

// ---------------------------------------------------------------------------
// Kernel 3: exclusive prefix over chunks (in place, layout-agnostic).
// ---------------------------------------------------------------------------
__global__ void prefix_kernel()
{
    int bh    = blockIdx.x >> 5;
    int slice = blockIdx.x & 31;
    int e = slice * 256 + threadIdx.x;
    size_t base = (size_t)bh * NCH * (Dc * Mc) + e;

    float acc = 0.f;
    #pragma unroll 1
    for (int c0 = 0; c0 < 64; c0 += 8) {
        float v[8];
        #pragma unroll
        for (int u = 0; u < 8; u++) v[u] = g_state[base + (size_t)(c0 + u) * (Dc * Mc)];
        #pragma unroll
        for (int u = 0; u < 8; u++) {
            g_state[base + (size_t)(c0 + u) * (Dc * Mc)] = acc;
            acc += v[u];
        }
    }

    if (slice == 0 && threadIdx.x < 128) {
        size_t kb = (size_t)bh * NCH * Mc + threadIdx.x;
        float a2 = 0.f;
        #pragma unroll 1
        for (int c = 0; c < 64; c++) {
            float t = g_ksum[kb + (size_t)c * Mc];
            g_ksum[kb + (size_t)c * Mc] = a2;
            a2 += t;
        }
    }
}

// ---------------------------------------------------------------------------
// Kernel 4: intra-chunk attention + state contribution + normalize.
// All tiles arrive in consumption layout: straight float4 copies, no scatters.
// XOR swizzle at 16B granularity: group(col,m) = (col>>2) ^ (m&15), pitch 68.
// ---------------------------------------------------------------------------
#define CMP 68
#define VP  68
#define AP  65
#define SM4_FLOATS (128*CMP /*q*/ + 128*CMP /*k|st union*/ + 64*VP + 64*AP + 128 + 64)

__device__ __forceinline__ int cm_idx(int m, int col) {
    return m * CMP + 4 * ((col >> 2) ^ (m & 15)) + (col & 3);
}

__global__ void __launch_bounds__(256, 2)
out_kernel(const float* __restrict__ vg, float* __restrict__ outg)
{
    extern __shared__ float sm[];
    float* q_s  = sm;                    // [m][i] swizzled
    float* u_s  = q_s + 128 * CMP;       // union: k [m][j] / state [m][d], both swizzled
    float* v_s  = u_s + 128 * CMP;       // [j][d] swizzled
    float* a_s  = v_s + 64 * VP;         // [i][j] pitch 65
    float* ks_s = a_s + 64 * AP;         // [m]
    float* den_s = ks_s + 128;           // [i]

    int tid = threadIdx.x;
    int bh  = blockIdx.x >> 6;
    int c   = blockIdx.x & 63;
    int b = bh >> 3, h = bh & 7;

    const float4* qsrc = (const float4*)&g_qp[((size_t)bh * Lc + c * 64) * Mc];  // [m][64]
    const float4* ksrc = (const float4*)&g_kp[((size_t)bh * Lc + c * 64) * Mc];  // [m][64]
    const float4* ssrc = (const float4*)&g_state[(size_t)blockIdx.x * (Dc * Mc)]; // [m][64]

    // Prefetch state into registers (goes into u_s after phase 1)
    float4 stv[8];
    #pragma unroll
    for (int k2 = 0; k2 < 8; k2++) stv[k2] = ssrc[tid + k2 * 256];

    // Q^T copy: [m][col] -> swizzled group
    #pragma unroll
    for (int t = tid; t < 2048; t += 256) {
        float4 w = qsrc[t];
        int m = t >> 4, c4 = t & 15;
        *(float4*)&q_s[m * CMP + 4 * (c4 ^ (m & 15))] = w;
    }
    // K^T copy into union buffer
    #pragma unroll
    for (int t = tid; t < 2048; t += 256) {
        float4 w = ksrc[t];
        int m = t >> 4, c4 = t & 15;
        *(float4*)&u_s[m * CMP + 4 * (c4 ^ (m & 15))] = w;
    }
    // V gather (rows strided in global), swizzled store
    #pragma unroll
    for (int t = tid; t < 1024; t += 256) {
        int row = t >> 4, col4 = t & 15;
        int l = c * 64 + row;
        const float4* src = (const float4*)(vg + (((size_t)b * Lc + l) * Hc + h) * Dc);
        *(float4*)&v_s[row * VP + 4 * (col4 ^ (row & 15))] = src[col4];
    }
    if (tid < 128) ks_s[tid] = g_ksum[(size_t)blockIdx.x * Mc + tid];
    __syncthreads();

    // --- phase 1: A = Q K^T (masked), FFMA2 ---
    {
        int jg = tid & 15, ig = tid >> 4;
        int i0 = ig * 4, j0 = jg * 4;
        ull acc[4][2];
        #pragma unroll
        for (int x = 0; x < 4; x++) { acc[x][0] = 0ull; acc[x][1] = 0ull; }

        if (j0 <= i0 + 3) {
            #pragma unroll 2
            for (int m = 0; m < 128; m++) {
                ulonglong2 qv = *(const ulonglong2*)&q_s[m * CMP + 4 * (ig ^ (m & 15))];
                ulonglong2 kv = *(const ulonglong2*)&u_s[m * CMP + 4 * (jg ^ (m & 15))];
                float q0, q1, q2, q3;
                unpack2(qv.x, q0, q1);
                unpack2(qv.y, q2, q3);
                ull qb0 = bcast2(q0), qb1 = bcast2(q1), qb2 = bcast2(q2), qb3 = bcast2(q3);
                ffma2(acc[0][0], qb0, kv.x); ffma2(acc[0][1], qb0, kv.y);
                ffma2(acc[1][0], qb1, kv.x); ffma2(acc[1][1], qb1, kv.y);
                ffma2(acc[2][0], qb2, kv.x); ffma2(acc[2][1], qb2, kv.y);
                ffma2(acc[3][0], qb3, kv.x); ffma2(acc[3][1], qb3, kv.y);
            }
        }
        #pragma unroll
        for (int x = 0; x < 4; x++) {
            int i = i0 + x;
            float a0, a1, a2, a3;
            unpack2(acc[x][0], a0, a1);
            unpack2(acc[x][1], a2, a3);
            a_s[i * AP + j0 + 0] = (j0 + 0 <= i) ? a0 : 0.f;
            a_s[i * AP + j0 + 1] = (j0 + 1 <= i) ? a1 : 0.f;
            a_s[i * AP + j0 + 2] = (j0 + 2 <= i) ? a2 : 0.f;
            a_s[i * AP + j0 + 3] = (j0 + 3 <= i) ? a3 : 0.f;
        }
    }
    __syncthreads();   // k reads done; a_s complete

    // scatter prefetched state into union buffer (same swizzled copy pattern)
    #pragma unroll
    for (int k2 = 0; k2 < 8; k2++) {
        int t = tid + k2 * 256;
        int m = t >> 4, c4 = t & 15;
        *(float4*)&u_s[m * CMP + 4 * (c4 ^ (m & 15))] = stv[k2];
    }

    // den
    if (tid < 64) {
        int i = tid;
        float dd = 0.f;
        #pragma unroll 4
        for (int m = 0; m < 128; m++) dd = fmaf(q_s[cm_idx(m, i)], ks_s[m], dd);
        for (int j = 0; j <= i; j++) dd += a_s[i * AP + j];
        den_s[i] = dd;
    }
    __syncthreads();

    // --- phase 2: num = Q*state + A*V, normalize.  FFMA2 ---
    int dg = tid & 7, igp = tid >> 3;
    int d0 = dg * 8, i0 = igp * 2;

    ull num0[4], num1[4];
    #pragma unroll
    for (int p = 0; p < 4; p++) { num0[p] = 0ull; num1[p] = 0ull; }

    {
        int grp = igp >> 1, off = i0 & 3;
        int g0 = d0 >> 2, g1 = (d0 >> 2) + 1;
        #pragma unroll 2
        for (int m = 0; m < 128; m++) {
            ull qp = *(const ull*)&q_s[m * CMP + 4 * (grp ^ (m & 15)) + off];
            float q0, q1; unpack2(qp, q0, q1);
            ull qb0 = bcast2(q0), qb1 = bcast2(q1);
            ulonglong2 s0 = *(const ulonglong2*)&u_s[m * CMP + 4 * (g0 ^ (m & 15))];
            ulonglong2 s1 = *(const ulonglong2*)&u_s[m * CMP + 4 * (g1 ^ (m & 15))];
            ffma2(num0[0], qb0, s0.x); ffma2(num0[1], qb0, s0.y);
            ffma2(num0[2], qb0, s1.x); ffma2(num0[3], qb0, s1.y);
            ffma2(num1[0], qb1, s0.x); ffma2(num1[1], qb1, s0.y);
            ffma2(num1[2], qb1, s1.x); ffma2(num1[3], qb1, s1.y);
        }
    }

    {
        int g0 = d0 >> 2, g1 = (d0 >> 2) + 1;
        #pragma unroll 2
        for (int j = 0; j <= i0 + 1; j++) {
            float a0 = a_s[i0 * AP + j];
            float a1 = a_s[(i0 + 1) * AP + j];
            ull ab0 = bcast2(a0), ab1 = bcast2(a1);
            ulonglong2 w0 = *(const ulonglong2*)&v_s[j * VP + 4 * (g0 ^ (j & 15))];
            ulonglong2 w1 = *(const ulonglong2*)&v_s[j * VP + 4 * (g1 ^ (j & 15))];
            ffma2(num0[0], ab0, w0.x); ffma2(num0[1], ab0, w0.y);
            ffma2(num0[2], ab0, w1.x); ffma2(num0[3], ab0, w1.y);
            ffma2(num1[0], ab1, w0.x); ffma2(num1[1], ab1, w0.y);
            ffma2(num1[2], ab1, w1.x); ffma2(num1[3], ab1, w1.y);
        }
    }

    // write out
    {
        float f[2][8];
        unpack2(num0[0], f[0][0], f[0][1]); unpack2(num0[1], f[0][2], f[0][3]);
        unpack2(num0[2], f[0][4], f[0][5]); unpack2(num0[3], f[0][6], f[0][7]);
        unpack2(num1[0], f[1][0], f[1][1]); unpack2(num1[1], f[1][2], f[1][3]);
        unpack2(num1[2], f[1][4], f[1][5]); unpack2(num1[3], f[1][6], f[1][7]);
        #pragma unroll
        for (int r = 0; r < 2; r++) {
            int i = i0 + r;
            int l = c * 64 + i;
            float inv = __fdividef(1.f, den_s[i]);
            float* orow = outg + (((size_t)b * Lc + l) * Hc + h) * Dc;
            *(float4*)&orow[d0]     = make_float4(f[r][0]*inv, f[r][1]*inv, f[r][2]*inv, f[r][3]*inv);
            *(float4*)&orow[d0 + 4] = make_float4(f[r][4]*inv, f[r][5]*inv, f[r][6]*inv, f[r][7]*inv);
        }
    }
}

// ---------------------------------------------------------------------------
extern "C" void kernel_launch(void* const* d_in, const int* in_sizes, int n_in,
                              void* d_out, int out_size)
{
    const float* q    = (const float*)d_in[0];
    const float* k    = (const float*)d_in[1];
    const float* v    = (const float*)d_in[2];
    const float* proj = (const float*)d_in[3];
    float* out = (float*)d_out;

    cudaFuncSetAttribute(proj_kernel, cudaFuncAttributeMaxDynamicSharedMemorySize,
                         PJ_SMEM * (int)sizeof(float));
    cudaFuncSetAttribute(chunk_kernel, cudaFuncAttributeMaxDynamicSharedMemorySize,
                         CK_SMEM * (int)sizeof(float));
    cudaFuncSetAttribute(out_kernel, cudaFuncAttributeMaxDynamicSharedMemorySize,
                         SM4_FLOATS * (int)sizeof(float));

    proj_kernel<<<2048, 256, PJ_SMEM * (int)sizeof(float)>>>(q, k, proj);
    chunk_kernel<<<BH * NCH, 256, CK_SMEM * (int)sizeof(float)>>>(v);
    prefix_kernel<<<BH * 32, 256>>>();
    out_kernel<<<BH * NCH, 256, SM4_FLOATS * (int)sizeof(float)>>>(v, out);
}